// round 12
// baseline (speedup 1.0000x reference)
#include <cuda_runtime.h>
#include <cuda_fp16.h>
#include <cstdint>

#define PB   8192
#define PDIM 4096
#define PHID 256
#define PH   16
#define PSEQ 2048

// -------- device-global scratch (no allocs allowed) --------
__device__ __align__(128) __half g_hidden[(size_t)PB * PDIM];   // 64 MB (fp16 GEMM1 out)
__device__ __align__(128) __half g_Xh[(size_t)PB * PDIM];       // 64 MB (fp16 x)
__device__ __align__(128) __half g_Wpt[(size_t)PH * PHID * PDIM]; // 32 MB [n_global][k]
__device__ __align__(128) __half g_Wot[(size_t)PDIM * PDIM];    // 32 MB [n][k]
__device__ float g_coef[48];                                    // w[16], cc[16], b[16]

// -------- helpers --------
__device__ __forceinline__ uint32_t smem_u32(const void* p) {
    uint32_t a;
    asm("{ .reg .u64 t; cvta.to.shared.u64 t, %1; cvt.u32.u64 %0, t; }" : "=r"(a) : "l"(p));
    return a;
}
__device__ __forceinline__ void cp16(uint32_t dst, const void* src) {
    asm volatile("cp.async.cg.shared.global [%0], [%1], 16;" :: "r"(dst), "l"(src));
}
__device__ __forceinline__ void ldsm4(uint32_t* r, uint32_t addr) {
    asm volatile("ldmatrix.sync.aligned.m8n8.x4.shared.b16 {%0,%1,%2,%3}, [%4];"
                 : "=r"(r[0]), "=r"(r[1]), "=r"(r[2]), "=r"(r[3]) : "r"(addr));
}
// m16n8k16 fp16 inputs, f32 accumulate
__device__ __forceinline__ void mma_f16(float* d, const uint32_t* a, uint32_t b0, uint32_t b1) {
    asm volatile("mma.sync.aligned.m16n8k16.row.col.f32.f16.f16.f32 "
                 "{%0,%1,%2,%3}, {%4,%5,%6,%7}, {%8,%9}, {%0,%1,%2,%3};"
                 : "+f"(d[0]), "+f"(d[1]), "+f"(d[2]), "+f"(d[3])
                 : "r"(a[0]), "r"(a[1]), "r"(a[2]), "r"(a[3]), "r"(b0), "r"(b1));
}

// -------- small prep kernels --------
__global__ void coef_kernel(const float* __restrict__ w_mix,
                            const float* __restrict__ b_mix,
                            const float* __restrict__ decay_values,
                            const int* __restrict__ index_p) {
    int h = threadIdx.x;
    if (h < PH) {
        int idx = *index_p;
        float w = w_mix[h * PSEQ + idx];
        float b = b_mix[h * PSEQ + idx];
        float d = decay_values[h];
        d = fminf(fmaxf(d, 0.9f), 1.0f);
        d = powf(d, 0.25f);
        g_coef[h]      = w;
        g_coef[16 + h] = (h < PH / 2) ? (w * d) : d;
        g_coef[32 + h] = b;
    }
}

// f32 -> f16 convert, 8 elems/thread
__global__ void cvt_half_kernel(const float* __restrict__ in, __half* __restrict__ out, int n8) {
    int i = blockIdx.x * blockDim.x + threadIdx.x;
    if (i < n8) {
        float4 v0 = ((const float4*)in)[i * 2];
        float4 v1 = ((const float4*)in)[i * 2 + 1];
        __half2 h[4];
        h[0] = __floats2half2_rn(v0.x, v0.y);
        h[1] = __floats2half2_rn(v0.z, v0.w);
        h[2] = __floats2half2_rn(v1.x, v1.y);
        h[3] = __floats2half2_rn(v1.z, v1.w);
        ((uint4*)out)[i] = *(uint4*)h;
    }
}

// out[b][c][r] = f16(in[b][r][c])
__global__ void transpose_half_kernel(const float* __restrict__ in, __half* __restrict__ out,
                                      int rows, int cols) {
    __shared__ float t[32][33];
    const float* In = in + (size_t)blockIdx.z * rows * cols;
    __half* Out = out + (size_t)blockIdx.z * rows * cols;
    int r0 = blockIdx.y * 32, c0 = blockIdx.x * 32;
#pragma unroll
    for (int i = threadIdx.y; i < 32; i += 8)
        t[i][threadIdx.x] = In[(size_t)(r0 + i) * cols + c0 + threadIdx.x];
    __syncthreads();
#pragma unroll
    for (int i = threadIdx.y; i < 32; i += 8)
        Out[(size_t)(c0 + i) * rows + r0 + threadIdx.x] = __float2half_rn(t[threadIdx.x][i]);
}

// -------- FP16 mma.sync GEMM: C[8192,4096] = A[8192,4096] @ Bt[4096,4096]^T --------
// Tile 128x256x64, 512 threads / 16 warps (2Mx8N -> 64x32 warp tiles),
// 4-stage cp.async (192 KB smem), occ 1 but 16 warps/SM (4/SMSP).
// Warp-count of R8 + smem:tensor ratio of R7.
// MODE 1: head epilogue -> fp16 hidden (head = blockIdx.x); MODE 2: +bias -> f32 out.
template <int MODE>
__global__ void __launch_bounds__(512, 1)
gemm_mma(const __half* __restrict__ A, const __half* __restrict__ Bt,
         const float* __restrict__ bias, const float* __restrict__ caches,
         void* __restrict__ Cv) {
    constexpr int S = 4;
    constexpr int BK = 64;                     // f16 elems per stage
    constexpr int NCH = PDIM / BK;             // 64
    constexpr uint32_t A_BYTES = 128 * 128;    // 16 KB (128 rows x 128B)
    constexpr uint32_t STG = A_BYTES + 256 * 128;  // 48 KB

    extern __shared__ char smem[];
    const uint32_t sb = smem_u32(smem);
    const int tid = threadIdx.x;
    const int wid = tid >> 5, lane = tid & 31;
    const int wm = wid & 1;      // 2 warps along M (64 rows each)
    const int wn = wid >> 1;     // 8 warps along N (32 cols each)

    const int m0 = blockIdx.y * 128;
    const int n0 = blockIdx.x * 256;
    const __half* Ab = A + (size_t)m0 * PDIM;
    const __half* Bb = Bt + (size_t)n0 * PDIM;

    // cp.async coords: A 1024 chunks (2/thr), B 2048 chunks (4/thr); chunk=16B
    int ar[2], ac[2]; uint32_t asw[2];
    int br[4], bc[4]; uint32_t bsw[4];
#pragma unroll
    for (int j = 0; j < 2; j++) {
        int id = tid + j * 512;
        ar[j] = id >> 3; ac[j] = id & 7;
        asw[j] = (uint32_t)ar[j] * 128 + ((((uint32_t)ac[j]) * 16) ^ ((((uint32_t)ar[j]) & 7) << 4));
    }
#pragma unroll
    for (int j = 0; j < 4; j++) {
        int id = tid + j * 512;
        br[j] = id >> 3; bc[j] = id & 7;
        bsw[j] = (uint32_t)br[j] * 128 + ((((uint32_t)bc[j]) * 16) ^ ((((uint32_t)br[j]) & 7) << 4));
    }

    float acc[4][4][4];
#pragma unroll
    for (int mt = 0; mt < 4; mt++)
#pragma unroll
        for (int nt = 0; nt < 4; nt++)
#pragma unroll
            for (int e = 0; e < 4; e++) acc[mt][nt][e] = 0.0f;

    // ldmatrix lane mapping: row = (lane&7)+((lane>>3)&1)*8, 16B group = lane>>4
    const int lrow = (lane & 7) + (((lane >> 3) & 1) << 3);
    const int lgrp = lane >> 4;
    const int a_row = wm * 64 + lrow;   // + mt*16
    const int b_row = wn * 32 + lrow;   // + ntp*16

    auto issue = [&](int c) {
        const __half* ag = Ab + c * BK;
        const __half* bg = Bb + c * BK;
        uint32_t st = sb + (uint32_t)(c & (S - 1)) * STG;
#pragma unroll
        for (int j = 0; j < 2; j++)
            cp16(st + asw[j], ag + (size_t)ar[j] * PDIM + ac[j] * 8);
#pragma unroll
        for (int j = 0; j < 4; j++)
            cp16(st + A_BYTES + bsw[j], bg + (size_t)br[j] * PDIM + bc[j] * 8);
    };

    // prologue: 3 stages
#pragma unroll
    for (int c = 0; c < S - 1; c++) {
        issue(c);
        asm volatile("cp.async.commit_group;" ::: "memory");
    }

    for (int i = 0; i < NCH; i++) {
        asm volatile("cp.async.wait_group %0;" :: "n"(S - 2) : "memory");
        __syncthreads();

        uint32_t sa = sb + (uint32_t)(i & (S - 1)) * STG;
        uint32_t sB = sa + A_BYTES;

#pragma unroll
        for (int ks = 0; ks < 4; ks++) {          // 4 x k16
            const int gg = 2 * ks + lgrp;
            uint32_t af[4][4], bf[2][4];
#pragma unroll
            for (int mt = 0; mt < 4; mt++) {
                int rr = a_row + mt * 16;
                ldsm4(af[mt], sa + (uint32_t)rr * 128 +
                              ((((uint32_t)gg) << 4) ^ ((((uint32_t)rr) & 7) << 4)));
            }
#pragma unroll
            for (int ntp = 0; ntp < 2; ntp++) {
                int rr = b_row + ntp * 16;
                ldsm4(bf[ntp], sB + (uint32_t)rr * 128 +
                               ((((uint32_t)gg) << 4) ^ ((((uint32_t)rr) & 7) << 4)));
            }
#pragma unroll
            for (int mt = 0; mt < 4; mt++)
#pragma unroll
                for (int nt = 0; nt < 4; nt++)
                    mma_f16(acc[mt][nt], af[mt],
                            bf[nt >> 1][nt & 1], bf[nt >> 1][(nt & 1) + 2]);
        }

        int c = i + S - 1;
        if (c < NCH) issue(c);
        asm volatile("cp.async.commit_group;" ::: "memory");
    }

    // -------- epilogue --------
    const int r = lane >> 2, qc = lane & 3;
    float wv = 0.f, ccf = 0.f, bvv = 0.f;
    if (MODE == 1) {
        wv  = g_coef[blockIdx.x];
        ccf = g_coef[16 + blockIdx.x];
        bvv = g_coef[32 + blockIdx.x];
    }
#pragma unroll
    for (int mt = 0; mt < 4; mt++) {
        const int grow0 = m0 + wm * 64 + mt * 16 + r;
#pragma unroll
        for (int nt = 0; nt < 4; nt++) {
            const int cloc = wn * 32 + nt * 8 + 2 * qc;   // col within 256-wide tile
            const int gcol = n0 + cloc;
            if (MODE == 1) {
                __half* C = (__half*)Cv;
                const float2 bp = *(const float2*)&bias[blockIdx.x * PHID + cloc];
#pragma unroll
                for (int h2 = 0; h2 < 2; h2++) {
                    const int grow = grow0 + h2 * 8;
                    const float2 cv = *(const float2*)
                        &caches[((size_t)blockIdx.x * PB + grow) * PHID + cloc];
                    __half2 o = __floats2half2_rn(
                        wv * (acc[mt][nt][h2 * 2 + 0] + bp.x) + ccf * cv.x + bvv,
                        wv * (acc[mt][nt][h2 * 2 + 1] + bp.y) + ccf * cv.y + bvv);
                    *(__half2*)&C[(size_t)grow * PDIM + gcol] = o;
                }
            } else {
                float* C = (float*)Cv;
                const float2 bp = *(const float2*)&bias[gcol];
#pragma unroll
                for (int h2 = 0; h2 < 2; h2++) {
                    const int grow = grow0 + h2 * 8;
                    float2 o;
                    o.x = acc[mt][nt][h2 * 2 + 0] + bp.x;
                    o.y = acc[mt][nt][h2 * 2 + 1] + bp.y;
                    *(float2*)&C[(size_t)grow * PDIM + gcol] = o;
                }
            }
        }
    }
}

// -------- launch --------
extern "C" void kernel_launch(void* const* d_in, const int* in_sizes, int n_in,
                              void* d_out, int out_size) {
    const float* x       = (const float*)d_in[0];
    const int*   index_p = (const int*)  d_in[1];
    const float* W_proj  = (const float*)d_in[2];
    const float* b_proj  = (const float*)d_in[3];
    const float* W_out   = (const float*)d_in[4];
    const float* b_out   = (const float*)d_in[5];
    const float* w_mix   = (const float*)d_in[6];
    const float* b_mix   = (const float*)d_in[7];
    const float* decay   = (const float*)d_in[8];
    const float* caches  = (const float*)d_in[9];
    float* out = (float*)d_out;

    __half *hidden, *xh, *wpt, *wot;
    cudaGetSymbolAddress((void**)&hidden, g_hidden);
    cudaGetSymbolAddress((void**)&xh,     g_Xh);
    cudaGetSymbolAddress((void**)&wpt,    g_Wpt);
    cudaGetSymbolAddress((void**)&wot,    g_Wot);

    const int SMEM_TOTAL = 4 * (128 * 128 + 256 * 128);   // 196608 (192 KB)
    cudaFuncSetAttribute(gemm_mma<1>, cudaFuncAttributeMaxDynamicSharedMemorySize, SMEM_TOTAL);
    cudaFuncSetAttribute(gemm_mma<2>, cudaFuncAttributeMaxDynamicSharedMemorySize, SMEM_TOTAL);

    coef_kernel<<<1, 32>>>(w_mix, b_mix, decay, index_p);

    // x -> fp16
    {
        int n8 = (int)(((size_t)PB * PDIM) / 8);
        cvt_half_kernel<<<(n8 + 255) / 256, 256>>>(x, xh, n8);
    }
    // W_proj [16][4096][256] -> g_Wpt fp16 [16][256][4096]
    transpose_half_kernel<<<dim3(PHID / 32, PDIM / 32, PH), dim3(32, 8)>>>(W_proj, wpt, PDIM, PHID);
    // W_out [4096][4096] -> g_Wot fp16 [N][K]
    transpose_half_kernel<<<dim3(PDIM / 32, PDIM / 32, 1), dim3(32, 8)>>>(W_out, wot, PDIM, PDIM);

    dim3 grid(PDIM / 256, PB / 128);   // (16, 64)
    gemm_mma<1><<<grid, 512, SMEM_TOTAL>>>(xh, wpt, b_proj, caches, hidden);
    gemm_mma<2><<<grid, 512, SMEM_TOTAL>>>(hidden, wot, b_out, nullptr, out);
}

// round 14
// speedup vs baseline: 1.2512x; 1.2512x over previous
#include <cuda_runtime.h>
#include <cuda_fp16.h>
#include <cstdint>

#define PB   8192
#define PDIM 4096
#define PHID 256
#define PH   16
#define PSEQ 2048

// -------- device-global scratch (no allocs allowed) --------
__device__ __align__(128) __half g_hidden[(size_t)PB * PDIM];    // 64 MB (fp16 GEMM1 out)
__device__ __align__(128) __half g_Xh[(size_t)PB * PDIM];        // 64 MB (fp16 x)
__device__ __align__(128) __half g_Wp16[(size_t)PH * PDIM * PHID]; // 32 MB, native [h][K][N]
__device__ __align__(128) __half g_Wo16[(size_t)PDIM * PDIM];    // 32 MB, native [K][N]
__device__ float g_coef[48];                                     // w[16], cc[16], b[16]

// -------- helpers --------
__device__ __forceinline__ uint32_t smem_u32(const void* p) {
    uint32_t a;
    asm("{ .reg .u64 t; cvta.to.shared.u64 t, %1; cvt.u32.u64 %0, t; }" : "=r"(a) : "l"(p));
    return a;
}
__device__ __forceinline__ void cp16(uint32_t dst, const void* src) {
    asm volatile("cp.async.cg.shared.global [%0], [%1], 16;" :: "r"(dst), "l"(src));
}
__device__ __forceinline__ void ldsm4(uint32_t* r, uint32_t addr) {
    asm volatile("ldmatrix.sync.aligned.m8n8.x4.shared.b16 {%0,%1,%2,%3}, [%4];"
                 : "=r"(r[0]), "=r"(r[1]), "=r"(r[2]), "=r"(r[3]) : "r"(addr));
}
// transposing variant: loads 8x8 b16 matrices transposed -> k-adjacent pairs per thread
__device__ __forceinline__ void ldsm4t(uint32_t* r, uint32_t addr) {
    asm volatile("ldmatrix.sync.aligned.m8n8.x4.trans.shared.b16 {%0,%1,%2,%3}, [%4];"
                 : "=r"(r[0]), "=r"(r[1]), "=r"(r[2]), "=r"(r[3]) : "r"(addr));
}
// m16n8k16 fp16 inputs, f32 accumulate
__device__ __forceinline__ void mma_f16(float* d, const uint32_t* a, uint32_t b0, uint32_t b1) {
    asm volatile("mma.sync.aligned.m16n8k16.row.col.f32.f16.f16.f32 "
                 "{%0,%1,%2,%3}, {%4,%5,%6,%7}, {%8,%9}, {%0,%1,%2,%3};"
                 : "+f"(d[0]), "+f"(d[1]), "+f"(d[2]), "+f"(d[3])
                 : "r"(a[0]), "r"(a[1]), "r"(a[2]), "r"(a[3]), "r"(b0), "r"(b1));
}

// -------- prep kernels --------
__global__ void coef_kernel(const float* __restrict__ w_mix,
                            const float* __restrict__ b_mix,
                            const float* __restrict__ decay_values,
                            const int* __restrict__ index_p) {
    int h = threadIdx.x;
    if (h < PH) {
        int idx = *index_p;
        float w = w_mix[h * PSEQ + idx];
        float b = b_mix[h * PSEQ + idx];
        float d = decay_values[h];
        d = fminf(fmaxf(d, 0.9f), 1.0f);
        d = powf(d, 0.25f);
        g_coef[h]      = w;
        g_coef[16 + h] = (h < PH / 2) ? (w * d) : d;
        g_coef[32 + h] = b;
    }
}

// single fused f32->f16 convert for x, W_proj, W_out (8 elems/thread)
__global__ void cvt3_kernel(const float* __restrict__ x,  __half* __restrict__ xo,
                            const float* __restrict__ wp, __half* __restrict__ wpo,
                            const float* __restrict__ wo, __half* __restrict__ woo) {
    const size_t NX = (size_t)PB * PDIM / 8;          // 4194304
    const size_t NW = (size_t)PH * PDIM * PHID / 8;   // 2097152
    size_t i = (size_t)blockIdx.x * blockDim.x + threadIdx.x;
    const float* src; __half* dst; size_t j;
    if (i < NX)               { src = x;  dst = xo;  j = i; }
    else if (i < NX + NW)     { src = wp; dst = wpo; j = i - NX; }
    else if (i < NX + 2 * NW) { src = wo; dst = woo; j = i - NX - NW; }
    else return;
    float4 v0 = ((const float4*)src)[j * 2];
    float4 v1 = ((const float4*)src)[j * 2 + 1];
    __half2 h[4];
    h[0] = __floats2half2_rn(v0.x, v0.y);
    h[1] = __floats2half2_rn(v0.z, v0.w);
    h[2] = __floats2half2_rn(v1.x, v1.y);
    h[3] = __floats2half2_rn(v1.z, v1.w);
    ((uint4*)dst)[j] = *(uint4*)h;
}

// -------- FP16 mma.sync GEMM: C[8192,4096] = A[8192,4096] @ W (native [K][N]) --------
// Tile 128x128x64, 8 warps (2Mx4N -> 64x32 warp tiles), 3-stage cp.async,
// 96 KB smem/CTA -> 2 CTAs/SM.  A: k-major smem + normal ldmatrix.
// B: native n-contiguous rows -> [k][n] smem tile + ldmatrix.x4.trans (no pre-transpose!).
// MODE 1: W_proj (ldw=256, head=blockIdx.x>>1) -> fp16 hidden; MODE 2: W_out -> f32 out.
template <int MODE>
__global__ void __launch_bounds__(256, 2)
gemm_mma(const __half* __restrict__ A, const __half* __restrict__ W,
         const float* __restrict__ bias, const float* __restrict__ caches,
         void* __restrict__ Cv) {
    constexpr int S = 3;
    constexpr int BK = 64;                     // f16 elems per stage
    constexpr int NCH = PDIM / BK;             // 64
    constexpr uint32_t A_BYTES = 128 * 128;    // 16 KB (128 M-rows x 128B)
    constexpr uint32_t B_BYTES = 64 * 256;     // 16 KB (64 k-rows x 256B)
    constexpr uint32_t STG = A_BYTES + B_BYTES;  // 32 KB

    extern __shared__ char smem[];
    const uint32_t sb = smem_u32(smem);
    const int tid = threadIdx.x;
    const int wid = tid >> 5, lane = tid & 31;
    const int wm = wid & 1;      // 2 warps along M (64 rows each)
    const int wn = wid >> 1;     // 4 warps along N (32 cols each)

    const int m0 = blockIdx.y * 128;
    const __half* Ab = A + (size_t)m0 * PDIM;

    // B base: native row-major weights, n-contiguous
    const __half* Wb;
    int ldw;
    if (MODE == 1) {
        const int head = blockIdx.x >> 1;
        const int kkb  = (blockIdx.x & 1) * 128;
        Wb = W + (size_t)head * PDIM * PHID + kkb;
        ldw = PHID;                            // 256
    } else {
        Wb = W + blockIdx.x * 128;
        ldw = PDIM;                            // 4096
    }

    // A cp.async coords: 128 rows x 8 groups of 16B -> 1024 chunks, 4/thread
    int ar[4], ac[4]; uint32_t asw[4];
#pragma unroll
    for (int j = 0; j < 4; j++) {
        int id = tid + j * 256;
        ar[j] = id >> 3; ac[j] = id & 7;
        asw[j] = (uint32_t)ar[j] * 128 + ((((uint32_t)ac[j]) * 16) ^ ((((uint32_t)ar[j]) & 7) << 4));
    }
    // B cp.async coords: 64 k-rows x 16 groups of 16B -> 1024 chunks, 4/thread
    int bkr[4], bng[4]; uint32_t bsw[4];
#pragma unroll
    for (int j = 0; j < 4; j++) {
        int id = tid + j * 256;
        bkr[j] = id >> 4; bng[j] = id & 15;
        bsw[j] = (uint32_t)bkr[j] * 256 + (uint32_t)((bng[j] ^ (bkr[j] & 7)) * 16);
    }

    float acc[4][4][4];
#pragma unroll
    for (int mt = 0; mt < 4; mt++)
#pragma unroll
        for (int nt = 0; nt < 4; nt++)
#pragma unroll
            for (int e = 0; e < 4; e++) acc[mt][nt][e] = 0.0f;

    // A ldmatrix lane mapping (k-major, as before)
    const int lrow = (lane & 7) + (((lane >> 3) & 1) << 3);
    const int lgrp = lane >> 4;
    const int a_row = wm * 64 + lrow;        // + mt*16
    // B trans-ldmatrix lane mapping: lanes 0-15 -> k-rows 0-15, lanes 16-31 -> +8 n
    const int t_kr = lane & 15;              // + ks*16
    const int t_ng = lane >> 4;              // + wn*4 + ntp*2

    auto issue = [&](int c) {
        const __half* ag = Ab + c * BK;
        const __half* bg = Wb + (size_t)(c * BK) * ldw;
        uint32_t st = sb + (uint32_t)(c % S) * STG;
#pragma unroll
        for (int j = 0; j < 4; j++)
            cp16(st + asw[j], ag + (size_t)ar[j] * PDIM + ac[j] * 8);
#pragma unroll
        for (int j = 0; j < 4; j++)
            cp16(st + A_BYTES + bsw[j], bg + (size_t)bkr[j] * ldw + bng[j] * 8);
    };

    // prologue: 2 stages
#pragma unroll
    for (int c = 0; c < S - 1; c++) {
        issue(c);
        asm volatile("cp.async.commit_group;" ::: "memory");
    }

    for (int i = 0; i < NCH; i++) {
        asm volatile("cp.async.wait_group %0;" :: "n"(S - 2) : "memory");
        __syncthreads();

        uint32_t sa = sb + (uint32_t)(i % S) * STG;
        uint32_t sB = sa + A_BYTES;

#pragma unroll
        for (int ks = 0; ks < 4; ks++) {          // 4 x k16
            const int gg = 2 * ks + lgrp;
            uint32_t af[4][4], bf[2][4];
#pragma unroll
            for (int mt = 0; mt < 4; mt++) {
                int rr = a_row + mt * 16;
                ldsm4(af[mt], sa + (uint32_t)rr * 128 +
                              ((((uint32_t)gg) << 4) ^ ((((uint32_t)rr) & 7) << 4)));
            }
#pragma unroll
            for (int ntp = 0; ntp < 2; ntp++) {
                int kk = ks * 16 + t_kr;
                int ng = wn * 4 + ntp * 2 + t_ng;
                ldsm4t(bf[ntp], sB + (uint32_t)kk * 256 +
                                (uint32_t)((ng ^ (kk & 7)) * 16));
            }
            // bf[ntp]: r0,r1 = b0,b1 for n-subtile 0; r2,r3 for n-subtile 1
#pragma unroll
            for (int mt = 0; mt < 4; mt++)
#pragma unroll
                for (int nt = 0; nt < 4; nt++)
                    mma_f16(acc[mt][nt], af[mt],
                            bf[nt >> 1][(nt & 1) * 2], bf[nt >> 1][(nt & 1) * 2 + 1]);
        }

        int c = i + S - 1;
        if (c < NCH) issue(c);
        asm volatile("cp.async.commit_group;" ::: "memory");
    }

    // -------- epilogue --------
    const int r = lane >> 2, qc = lane & 3;
    const int hhead = blockIdx.x >> 1;
    const int kkb = (blockIdx.x & 1) * 128;
    float wv = 0.f, ccf = 0.f, bvv = 0.f;
    if (MODE == 1) {
        wv  = g_coef[hhead];
        ccf = g_coef[16 + hhead];
        bvv = g_coef[32 + hhead];
    }
#pragma unroll
    for (int mt = 0; mt < 4; mt++) {
        const int grow0 = m0 + wm * 64 + mt * 16 + r;
#pragma unroll
        for (int nt = 0; nt < 4; nt++) {
            const int cloc = wn * 32 + nt * 8 + 2 * qc;   // col within 128-wide tile
            const int gcol = blockIdx.x * 128 + cloc;
            if (MODE == 1) {
                __half* C = (__half*)Cv;
                const float2 bp = *(const float2*)&bias[hhead * PHID + kkb + cloc];
#pragma unroll
                for (int h2 = 0; h2 < 2; h2++) {
                    const int grow = grow0 + h2 * 8;
                    const float2 cv = *(const float2*)
                        &caches[((size_t)hhead * PB + grow) * PHID + kkb + cloc];
                    __half2 o = __floats2half2_rn(
                        wv * (acc[mt][nt][h2 * 2 + 0] + bp.x) + ccf * cv.x + bvv,
                        wv * (acc[mt][nt][h2 * 2 + 1] + bp.y) + ccf * cv.y + bvv);
                    *(__half2*)&C[(size_t)grow * PDIM + gcol] = o;
                }
            } else {
                float* C = (float*)Cv;
                const float2 bp = *(const float2*)&bias[gcol];
#pragma unroll
                for (int h2 = 0; h2 < 2; h2++) {
                    const int grow = grow0 + h2 * 8;
                    float2 o;
                    o.x = acc[mt][nt][h2 * 2 + 0] + bp.x;
                    o.y = acc[mt][nt][h2 * 2 + 1] + bp.y;
                    *(float2*)&C[(size_t)grow * PDIM + gcol] = o;
                }
            }
        }
    }
}

// -------- launch --------
extern "C" void kernel_launch(void* const* d_in, const int* in_sizes, int n_in,
                              void* d_out, int out_size) {
    const float* x       = (const float*)d_in[0];
    const int*   index_p = (const int*)  d_in[1];
    const float* W_proj  = (const float*)d_in[2];
    const float* b_proj  = (const float*)d_in[3];
    const float* W_out   = (const float*)d_in[4];
    const float* b_out   = (const float*)d_in[5];
    const float* w_mix   = (const float*)d_in[6];
    const float* b_mix   = (const float*)d_in[7];
    const float* decay   = (const float*)d_in[8];
    const float* caches  = (const float*)d_in[9];
    float* out = (float*)d_out;

    __half *hidden, *xh, *wp16, *wo16;
    cudaGetSymbolAddress((void**)&hidden, g_hidden);
    cudaGetSymbolAddress((void**)&xh,     g_Xh);
    cudaGetSymbolAddress((void**)&wp16,   g_Wp16);
    cudaGetSymbolAddress((void**)&wo16,   g_Wo16);

    const int SMEM_TOTAL = 3 * 2 * 128 * 128;   // 98304 (96 KB)
    cudaFuncSetAttribute(gemm_mma<1>, cudaFuncAttributeMaxDynamicSharedMemorySize, SMEM_TOTAL);
    cudaFuncSetAttribute(gemm_mma<2>, cudaFuncAttributeMaxDynamicSharedMemorySize, SMEM_TOTAL);

    coef_kernel<<<1, 32>>>(w_mix, b_mix, decay, index_p);

    // fused f32->f16 for x, W_proj, W_out (native layouts, no transposes)
    {
        const size_t total = (size_t)PB * PDIM / 8 + 2 * ((size_t)PH * PDIM * PHID / 8);
        cvt3_kernel<<<(unsigned)((total + 255) / 256), 256>>>(x, xh, W_proj, wp16, W_out, wo16);
    }

    dim3 grid(PDIM / 128, PB / 128);   // (32, 64)
    gemm_mma<1><<<grid, 256, SMEM_TOTAL>>>(xh, wp16, b_proj, caches, hidden);
    gemm_mma<2><<<grid, 256, SMEM_TOTAL>>>(hidden, wo16, b_out, nullptr, out);
}